// round 14
// baseline (speedup 1.0000x reference)
#include <cuda_runtime.h>
#include <cuda_fp16.h>
#include <math.h>
#include <stdint.h>

#define BB   2
#define SS   2048
#define DD   1024
#define NH   16
#define HDIM 64
#define NTOK (BB*SS)

// Scratch (device globals: allocation-free per harness rules)
__device__ __half g_q[NTOK*DD];    // [b][h][s][d], pre-scaled by 0.125*log2(e)
__device__ __half g_k[NTOK*DD];
__device__ __half g_v[NTOK*DD];
__device__ __half g_ctx[NTOK*DD];  // [b][s][h*64+d]
__device__ __half g_x16[NTOK*DD];  // fp16 copy of x
__device__ __half g_wq16[DD*DD];
__device__ __half g_wk16[DD*DD];
__device__ __half g_wv16[DD*DD];
__device__ __half g_wo16[DD*DD];

// ---------------------------------------------------------------------------
// Helpers
// ---------------------------------------------------------------------------
__device__ __forceinline__ uint32_t smem_u32(const void* p) {
    uint32_t a;
    asm("{ .reg .u64 t; cvta.to.shared.u64 t, %1; cvt.u32.u64 %0, t; }"
        : "=r"(a) : "l"(p));
    return a;
}
__device__ __forceinline__ uint32_t f2h2(float lo, float hi) {
    __half2 h = __floats2half2_rn(lo, hi);
    return *reinterpret_cast<uint32_t*>(&h);
}
__device__ __forceinline__ uint32_t hsub2(uint32_t a, uint32_t b) {
    uint32_t d;
    asm("sub.f16x2 %0, %1, %2;" : "=r"(d) : "r"(a), "r"(b));
    return d;
}
__device__ __forceinline__ uint32_t ex2h2(uint32_t a) {
    uint32_t d;
    asm("ex2.approx.f16x2 %0, %1;" : "=r"(d) : "r"(a));
    return d;
}
__device__ __forceinline__ void mma_f16(float d[4], const uint32_t a[4],
                                        const uint32_t* b, const float c[4]) {
    asm volatile(
        "mma.sync.aligned.m16n8k16.row.col.f32.f16.f16.f32 "
        "{%0,%1,%2,%3}, {%4,%5,%6,%7}, {%8,%9}, {%10,%11,%12,%13};"
        : "=f"(d[0]), "=f"(d[1]), "=f"(d[2]), "=f"(d[3])
        : "r"(a[0]), "r"(a[1]), "r"(a[2]), "r"(a[3]),
          "r"(b[0]), "r"(b[1]),
          "f"(c[0]), "f"(c[1]), "f"(c[2]), "f"(c[3]));
}
__device__ __forceinline__ void ldsm_x4(uint32_t r[4], uint32_t addr) {
    asm volatile("ldmatrix.sync.aligned.m8n8.x4.shared.b16 {%0,%1,%2,%3}, [%4];"
        : "=r"(r[0]), "=r"(r[1]), "=r"(r[2]), "=r"(r[3]) : "r"(addr));
}
__device__ __forceinline__ void ldsm_x4_t(uint32_t r[4], uint32_t addr) {
    asm volatile("ldmatrix.sync.aligned.m8n8.x4.trans.shared.b16 {%0,%1,%2,%3}, [%4];"
        : "=r"(r[0]), "=r"(r[1]), "=r"(r[2]), "=r"(r[3]) : "r"(addr));
}
__device__ __forceinline__ void cp_async16(uint32_t saddr, const void* gaddr) {
    asm volatile("cp.async.cg.shared.global [%0], [%1], 16;"
        :: "r"(saddr), "l"(gaddr) : "memory");
}

// ---------------------------------------------------------------------------
// Kernel 0: single fused fp32 -> fp16 convert.
// grid (DD*DD/4/256, 8): y in [0,3] = Wq/Wk/Wv/Wo; y in [4,7] = quarters of x.
// ---------------------------------------------------------------------------
__global__ __launch_bounds__(256) void cvt_all_kernel(
    const float4* __restrict__ x,
    const float4* __restrict__ w0, const float4* __restrict__ w1,
    const float4* __restrict__ w2, const float4* __restrict__ w3,
    uint2* __restrict__ dx,
    uint2* __restrict__ d0, uint2* __restrict__ d1,
    uint2* __restrict__ d2, uint2* __restrict__ d3)
{
    const int nseg = DD*DD/4;   // elements (float4) per segment
    const int i = blockIdx.x * 256 + threadIdx.x;   // < nseg
    const int y = blockIdx.y;
    const float4* s;
    uint2* d;
    if (y < 4) {
        s = (y == 0) ? w0 : (y == 1) ? w1 : (y == 2) ? w2 : w3;
        d = (y == 0) ? d0 : (y == 1) ? d1 : (y == 2) ? d2 : d3;
    } else {
        const int off = (y - 4) * nseg;
        s = x + off;
        d = dx + off;
    }
    const float4 v = s[i];
    uint2 o;
    o.x = f2h2(v.x, v.y);
    o.y = f2h2(v.z, v.w);
    d[i] = o;
}

// ---------------------------------------------------------------------------
// fp16 GEMM core (round-10 proven config): C(128x256) = A @ B^T, K=1024.
// 256 thr = 8 warps (2x4), warp tile 64x64, BK=32, 4-stage cp.async.
// Smem/stage 24KB: A 128x32h at +0 (8KB), B 256x32h at +8192 (16KB).
// Swizzle: byte = row*64 + ((ch ^ ((row>>1)&3))*16), ch = k>>3.
// ---------------------------------------------------------------------------
#define GSTG 24576u

__device__ __forceinline__ void gemm16_stage(
    const __half* __restrict__ A, const __half* __restrict__ B,
    int m0, int n0, uint32_t sbase, int s, int k0, int tid)
{
    const uint32_t sb = sbase + (uint32_t)s*GSTG;
    #pragma unroll
    for (int j = 0; j < 2; j++) {
        const int id  = tid + j*256;
        const int row = id >> 2;
        const int ch  = id & 3;
        const uint32_t sw = (uint32_t)(row*64 + ((ch ^ ((row>>1)&3))*16));
        cp_async16(sb + sw, A + (size_t)(m0 + row)*DD + k0 + ch*8);
    }
    #pragma unroll
    for (int j = 0; j < 4; j++) {
        const int id  = tid + j*256;
        const int row = id >> 2;
        const int ch  = id & 3;
        const uint32_t sw = (uint32_t)(row*64 + ((ch ^ ((row>>1)&3))*16));
        cp_async16(sb + 8192u + sw, B + (size_t)(n0 + row)*DD + k0 + ch*8);
    }
    asm volatile("cp.async.commit_group;" ::: "memory");
}

__device__ __forceinline__ void gemm16_core(
    const __half* __restrict__ A, const __half* __restrict__ B,
    int m0, int n0, uint32_t sbase, float acc[4][8][4])
{
    const int tid  = threadIdx.x;
    const int lane = tid & 31;
    const int warp = tid >> 5;
    const int wm = warp >> 2;        // 0..1 (64 m-rows)
    const int wn = warp & 3;         // 0..3 (64 n-cols)

    const int a_row_off = (lane & 7) + ((lane >> 3) & 1) * 8;
    const int a_ch_off  = lane >> 4;
    const int b_row_off = ((lane >> 4) << 3) + (lane & 7);
    const int b_ch_off  = (lane >> 3) & 1;

    gemm16_stage(A, B, m0, n0, sbase, 0, 0,  tid);
    gemm16_stage(A, B, m0, n0, sbase, 1, 32, tid);
    gemm16_stage(A, B, m0, n0, sbase, 2, 64, tid);

    for (int i = 0; i < 32; i++) {
        if (i < 30)       { asm volatile("cp.async.wait_group 2;" ::: "memory"); }
        else if (i == 30) { asm volatile("cp.async.wait_group 1;" ::: "memory"); }
        else              { asm volatile("cp.async.wait_group 0;" ::: "memory"); }
        __syncthreads();

        if (i + 3 < 32)
            gemm16_stage(A, B, m0, n0, sbase, (i+3) & 3, (i+3)*32, tid);

        const uint32_t sA = sbase + (uint32_t)(i & 3)*GSTG;
        const uint32_t sB = sA + 8192u;

        #pragma unroll
        for (int ks = 0; ks < 2; ks++) {
            uint32_t af[4][4];
            #pragma unroll
            for (int mt = 0; mt < 4; mt++) {
                const int row = wm*64 + mt*16 + a_row_off;
                const int ch  = 2*ks + a_ch_off;
                ldsm_x4(af[mt], sA + (uint32_t)(row*64 + ((ch ^ ((row>>1)&3))*16)));
            }
            uint32_t bf[8][2];
            #pragma unroll
            for (int pr = 0; pr < 4; pr++) {
                const int row = wn*64 + pr*16 + b_row_off;
                const int ch  = 2*ks + b_ch_off;
                uint32_t t[4];
                ldsm_x4(t, sB + (uint32_t)(row*64 + ((ch ^ ((row>>1)&3))*16)));
                bf[pr*2  ][0] = t[0]; bf[pr*2  ][1] = t[1];
                bf[pr*2+1][0] = t[2]; bf[pr*2+1][1] = t[3];
            }
            #pragma unroll
            for (int mt = 0; mt < 4; mt++)
                #pragma unroll
                for (int nt = 0; nt < 8; nt++)
                    mma_f16(acc[mt][nt], af[mt], bf[nt], acc[mt][nt]);
        }
    }
}

// ---------------------------------------------------------------------------
// Kernel 1: fused QKV projection. grid (4, 32, 3), block 256. fp16 in/out.
// ---------------------------------------------------------------------------
#define QSCALE 0.1803368801111743f   // 0.125 * log2(e)

__global__ __launch_bounds__(256) void qkv_gemm_kernel()
{
    extern __shared__ char smg[];
    const uint32_t sbase = smem_u32(smg);

    const __half* W   = (blockIdx.z == 0) ? g_wq16 : (blockIdx.z == 1) ? g_wk16 : g_wv16;
    __half*       out = (blockIdx.z == 0) ? g_q    : (blockIdx.z == 1) ? g_k    : g_v;
    const float oscale = (blockIdx.z == 0) ? QSCALE : 1.0f;

    const int m0 = blockIdx.y * 128;
    const int n0 = blockIdx.x * 256;

    float acc[4][8][4];
    #pragma unroll
    for (int i = 0; i < 4; i++)
        #pragma unroll
        for (int j = 0; j < 8; j++)
            #pragma unroll
            for (int k = 0; k < 4; k++) acc[i][j][k] = 0.f;

    gemm16_core(g_x16, W, m0, n0, sbase, acc);

    const int lane = threadIdx.x & 31;
    const int warp = threadIdx.x >> 5;
    const int wm = warp >> 2, wn = warp & 3;
    const int r = lane >> 2, c = lane & 3;

    #pragma unroll
    for (int mt = 0; mt < 4; mt++) {
        #pragma unroll
        for (int nt = 0; nt < 8; nt++) {
            #pragma unroll
            for (int half = 0; half < 2; half++) {
                const int m = m0 + wm*64 + mt*16 + r + half*8;
                const int b = m >> 11;
                const int s = m & 2047;
                const int n = n0 + wn*64 + nt*8 + c*2;
                const int h = n >> 6;
                const int d = n & 63;
                const uint32_t v = f2h2(acc[mt][nt][half*2+0]*oscale,
                                        acc[mt][nt][half*2+1]*oscale);
                *reinterpret_cast<uint32_t*>(
                    out + (((size_t)(b*NH + h))*SS + s)*HDIM + d) = v;
            }
        }
    }
}

// ---------------------------------------------------------------------------
// Kernel 3: output projection + bias. grid (4, 32), block 256.
// ---------------------------------------------------------------------------
__global__ __launch_bounds__(256) void oproj_kernel(
    const float* __restrict__ bo,
    float* __restrict__ out)
{
    extern __shared__ char smg[];
    const uint32_t sbase = smem_u32(smg);

    const int m0 = blockIdx.y * 128;
    const int n0 = blockIdx.x * 256;

    float acc[4][8][4];
    #pragma unroll
    for (int i = 0; i < 4; i++)
        #pragma unroll
        for (int j = 0; j < 8; j++)
            #pragma unroll
            for (int k = 0; k < 4; k++) acc[i][j][k] = 0.f;

    gemm16_core(g_ctx, g_wo16, m0, n0, sbase, acc);

    const int lane = threadIdx.x & 31;
    const int warp = threadIdx.x >> 5;
    const int wm = warp >> 2, wn = warp & 3;
    const int r = lane >> 2, c = lane & 3;

    #pragma unroll
    for (int mt = 0; mt < 4; mt++) {
        #pragma unroll
        for (int nt = 0; nt < 8; nt++) {
            #pragma unroll
            for (int half = 0; half < 2; half++) {
                const int m = m0 + wm*64 + mt*16 + r + half*8;
                const int n = n0 + wn*64 + nt*8 + c*2;
                float* o = out + (size_t)m*DD + n;
                o[0] = acc[mt][nt][half*2 + 0] + bo[n];
                o[1] = acc[mt][nt][half*2 + 1] + bo[n + 1];
            }
        }
    }
}

// ---------------------------------------------------------------------------
// Kernel 2: causal flash attention. 512 threads = 16 warps covering 256
// q-rows per CTA (2 q-tiles share each staged KV tile). grid (8, 32).
// log2 softmax, packed fp16 exp, l via P@ones mma, rescale skip,
// 2-stage KV cp.async pipeline (2x16KB smem).
// ---------------------------------------------------------------------------
#define ASTG 16384u

__global__ __launch_bounds__(512, 1) void attn_kernel()
{
    __shared__ __align__(16) char smA[2*ASTG];
    const uint32_t sbase = smem_u32(smA);

    const int tid  = threadIdx.x;
    const int lane = tid & 31;
    const int warp = tid >> 5;            // 0..15
    const int r = lane >> 2;
    const int c = lane & 3;
    const int pair = 7 - blockIdx.x;      // heavy CTAs first
    const int bh = blockIdx.y;

    const __half* Qg = g_q + (size_t)bh * SS * HDIM;
    const __half* Kg = g_k + (size_t)bh * SS * HDIM;
    const __half* Vg = g_v + (size_t)bh * SS * HDIM;
    const uint32_t* Qg2 = reinterpret_cast<const uint32_t*>(Qg);
    const int q0 = pair * 256;
    const int qbase = q0 + warp * 16;

    // Q fragments (g_q pre-scaled by 0.125*log2e)
    uint32_t qf[4][4];
    #pragma unroll
    for (int kk = 0; kk < 4; kk++) {
        qf[kk][0] = Qg2[(size_t)(qbase + r    )*32 + kk*8 + c    ];
        qf[kk][1] = Qg2[(size_t)(qbase + r + 8)*32 + kk*8 + c    ];
        qf[kk][2] = Qg2[(size_t)(qbase + r    )*32 + kk*8 + c + 4];
        qf[kk][3] = Qg2[(size_t)(qbase + r + 8)*32 + kk*8 + c + 4];
    }

    const int k_key_off = ((lane >> 4) & 1) * 8 + (lane & 7);
    const int k_ch_off  = (lane >> 3) & 1;
    const int v_key_off = ((lane >> 3) & 1) * 8 + (lane & 7);
    const int v_ch_off  = (lane >> 4);

    const uint32_t ones2[2] = { 0x3C003C00u, 0x3C003C00u };  // fp16 1.0 x2

    float of[8][4];
    #pragma unroll
    for (int nt = 0; nt < 8; nt++)
        #pragma unroll
        for (int j = 0; j < 4; j++) of[nt][j] = 0.f;
    float lc[4] = {0.f, 0.f, 0.f, 0.f};   // row-sum accumulator (P @ ones)
    float m0i = -1e30f, m1i = -1e30f;

    // stage KV tile kt into buffer s: 512 threads, 1 cp.async each for K and V
    auto stage = [&](int kt, int s) {
        const uint32_t sb = sbase + (uint32_t)s * ASTG;
        const int row = tid >> 3;          // 0..63 (key)
        const int ch  = tid & 7;
        const uint32_t sw = (uint32_t)(row*128 + ((ch ^ (row & 7))*16));
        cp_async16(sb + sw,          Kg + (size_t)(kt*64 + row)*HDIM + ch*8);
        cp_async16(sb + 8192u + sw,  Vg + (size_t)(kt*64 + row)*HDIM + ch*8);
        asm volatile("cp.async.commit_group;" ::: "memory");
    };

    const int ktmax = 4*pair + 3;         // last key tile for q rows q0..q0+255
    stage(0, 0);

    for (int kt = 0; kt <= ktmax; kt++) {
        asm volatile("cp.async.wait_group 0;" ::: "memory");
        __syncthreads();
        if (kt < ktmax) stage(kt + 1, (kt + 1) & 1);

        if (kt*64 > qbase + 15) continue;

        const uint32_t sK = sbase + (uint32_t)(kt & 1) * ASTG;
        const uint32_t sV = sK + 8192u;

        // ---- S = Q @ K^T (log2 domain) ----
        float sf[8][4];
        #pragma unroll
        for (int nt = 0; nt < 8; nt++)
            #pragma unroll
            for (int j = 0; j < 4; j++) sf[nt][j] = 0.f;

        #pragma unroll
        for (int kk = 0; kk < 4; kk++) {
            #pragma unroll
            for (int ntp = 0; ntp < 4; ntp++) {
                const int key = ntp*16 + k_key_off;
                const int ch  = 2*kk + k_ch_off;
                uint32_t t[4];
                ldsm_x4(t, sK + (uint32_t)(key*128 + ((ch ^ (key & 7))*16)));
                mma_f16(sf[2*ntp    ], qf[kk], &t[0], sf[2*ntp    ]);
                mma_f16(sf[2*ntp + 1], qf[kk], &t[2], sf[2*ntp + 1]);
            }
        }

        // ---- causal mask (boundary tiles only) ----
        const int qg0 = qbase + r;
        const int qg1 = qg0 + 8;
        if (kt*64 + 63 > qbase) {
            #pragma unroll
            for (int nt = 0; nt < 8; nt++) {
                const int col0 = kt*64 + nt*8 + c*2;
                if (col0     > qg0) sf[nt][0] = -1e30f;
                if (col0 + 1 > qg0) sf[nt][1] = -1e30f;
                if (col0     > qg1) sf[nt][2] = -1e30f;
                if (col0 + 1 > qg1) sf[nt][3] = -1e30f;
            }
        }

        // ---- online softmax (base-2, packed fp16 exp) ----
        float mx0 = -1e30f, mx1 = -1e30f;
        #pragma unroll
        for (int nt = 0; nt < 8; nt++) {
            mx0 = fmaxf(mx0, fmaxf(sf[nt][0], sf[nt][1]));
            mx1 = fmaxf(mx1, fmaxf(sf[nt][2], sf[nt][3]));
        }
        mx0 = fmaxf(mx0, __shfl_xor_sync(0xffffffffu, mx0, 1));
        mx0 = fmaxf(mx0, __shfl_xor_sync(0xffffffffu, mx0, 2));
        mx1 = fmaxf(mx1, __shfl_xor_sync(0xffffffffu, mx1, 1));
        mx1 = fmaxf(mx1, __shfl_xor_sync(0xffffffffu, mx1, 2));

        const float mn0 = fmaxf(m0i, mx0);
        const float mn1 = fmaxf(m1i, mx1);

        // packed exp: cvt pair -> HSUB2 broadcast max -> ex2.approx.f16x2
        const uint32_t mn0h2 = f2h2(mn0, mn0);
        const uint32_t mn1h2 = f2h2(mn1, mn1);
        uint32_t pk[4][4];
        #pragma unroll
        for (int nt = 0; nt < 8; nt++) {
            const uint32_t a = f2h2(sf[nt][0], sf[nt][1]);   // row0 pair
            const uint32_t b = f2h2(sf[nt][2], sf[nt][3]);   // row1 pair
            pk[nt >> 1][(nt & 1)*2    ] = ex2h2(hsub2(a, mn0h2));
            pk[nt >> 1][(nt & 1)*2 + 1] = ex2h2(hsub2(b, mn1h2));
        }

        // rescale accumulators only when a max moved (exact skip: cor==1)
        const bool chg = (mn0 > m0i) || (mn1 > m1i);
        if (__any_sync(0xffffffffu, chg)) {
            const float cor0 = exp2f(m0i - mn0);
            const float cor1 = exp2f(m1i - mn1);
            lc[0] *= cor0; lc[1] *= cor0; lc[2] *= cor1; lc[3] *= cor1;
            #pragma unroll
            for (int nt = 0; nt < 8; nt++) {
                of[nt][0] *= cor0;
                of[nt][1] *= cor0;
                of[nt][2] *= cor1;
                of[nt][3] *= cor1;
            }
        }
        m0i = mn0;
        m1i = mn1;

        // l += P @ ones (tensor pipe; lanes get their rows' sums in lc[0]/lc[2])
        #pragma unroll
        for (int kk = 0; kk < 4; kk++)
            mma_f16(lc, pk[kk], ones2, lc);

        // ---- O += P @ V ----
        #pragma unroll
        for (int kk = 0; kk < 4; kk++) {
            #pragma unroll
            for (int ntp = 0; ntp < 4; ntp++) {
                const int key = 16*kk + v_key_off;
                const int ch  = 2*ntp + v_ch_off;
                uint32_t t[4];
                ldsm_x4_t(t, sV + (uint32_t)(key*128 + ((ch ^ (key & 7))*16)));
                mma_f16(of[2*ntp    ], pk[kk], &t[0], of[2*ntp    ]);
                mma_f16(of[2*ntp + 1], pk[kk], &t[2], of[2*ntp + 1]);
            }
        }
    }

    // epilogue: normalize, write ctx (fp16) [b][s][h*64+d]
    const int b = bh >> 4, h = bh & 15;
    const float inv0 = 1.0f / lc[0];
    const float inv1 = 1.0f / lc[2];
    const int qg0 = qbase + r;
    #pragma unroll
    for (int nt = 0; nt < 8; nt++) {
        const int d = nt*8 + c*2;
        *reinterpret_cast<uint32_t*>(
            g_ctx + ((size_t)(b*SS + qg0    ))*DD + h*HDIM + d) = f2h2(of[nt][0]*inv0, of[nt][1]*inv0);
        *reinterpret_cast<uint32_t*>(
            g_ctx + ((size_t)(b*SS + qg0 + 8))*DD + h*HDIM + d) = f2h2(of[nt][2]*inv1, of[nt][3]*inv1);
    }
}

// ---------------------------------------------------------------------------
// Launch
// ---------------------------------------------------------------------------
extern "C" void kernel_launch(void* const* d_in, const int* in_sizes, int n_in,
                              void* d_out, int out_size)
{
    const float* x  = (const float*)d_in[0];
    const float* Wq = (const float*)d_in[1];
    const float* Wk = (const float*)d_in[2];
    const float* Wv = (const float*)d_in[3];
    const float* Wo = (const float*)d_in[4];
    const float* bo = (const float*)d_in[5];
    float* out = (float*)d_out;

    (void)in_sizes; (void)n_in; (void)out_size;

    __half* dx;  cudaGetSymbolAddress((void**)&dx,  g_x16);
    __half* dwq; cudaGetSymbolAddress((void**)&dwq, g_wq16);
    __half* dwk; cudaGetSymbolAddress((void**)&dwk, g_wk16);
    __half* dwv; cudaGetSymbolAddress((void**)&dwv, g_wv16);
    __half* dwo; cudaGetSymbolAddress((void**)&dwo, g_wo16);

    const int nseg = DD*DD/4;   // 256K float4 per segment
    cvt_all_kernel<<<dim3(nseg/256, 8), 256>>>(
        (const float4*)x,
        (const float4*)Wq, (const float4*)Wk, (const float4*)Wv, (const float4*)Wo,
        (uint2*)dx, (uint2*)dwq, (uint2*)dwk, (uint2*)dwv, (uint2*)dwo);

    const int gsm = 4 * GSTG;   // 98304 bytes dynamic smem (4-stage pipeline)
    cudaFuncSetAttribute(qkv_gemm_kernel,
                         cudaFuncAttributeMaxDynamicSharedMemorySize, gsm);
    cudaFuncSetAttribute(oproj_kernel,
                         cudaFuncAttributeMaxDynamicSharedMemorySize, gsm);

    qkv_gemm_kernel<<<dim3(4, 32, 3), 256, gsm>>>();
    attn_kernel<<<dim3(8, 32), 512>>>();
    oproj_kernel<<<dim3(4, 32), 256, gsm>>>(bo, out);
}

// round 15
// speedup vs baseline: 1.7846x; 1.7846x over previous
#include <cuda_runtime.h>
#include <cuda_fp16.h>
#include <math.h>
#include <stdint.h>

#define BB   2
#define SS   2048
#define DD   1024
#define NH   16
#define HDIM 64
#define NTOK (BB*SS)

// Scratch (device globals: allocation-free per harness rules)
__device__ __half g_q[NTOK*DD];    // [b][h][s][d], pre-scaled by 0.125*log2(e)
__device__ __half g_k[NTOK*DD];
__device__ __half g_v[NTOK*DD];
__device__ __half g_ctx[NTOK*DD];  // [b][s][h*64+d]
__device__ __half g_x16[NTOK*DD];  // fp16 copy of x
__device__ __half g_wq16[DD*DD];
__device__ __half g_wk16[DD*DD];
__device__ __half g_wv16[DD*DD];
__device__ __half g_wo16[DD*DD];

// ---------------------------------------------------------------------------
// Helpers
// ---------------------------------------------------------------------------
__device__ __forceinline__ uint32_t smem_u32(const void* p) {
    uint32_t a;
    asm("{ .reg .u64 t; cvta.to.shared.u64 t, %1; cvt.u32.u64 %0, t; }"
        : "=r"(a) : "l"(p));
    return a;
}
__device__ __forceinline__ uint32_t f2h2(float lo, float hi) {
    __half2 h = __floats2half2_rn(lo, hi);
    return *reinterpret_cast<uint32_t*>(&h);
}
__device__ __forceinline__ uint32_t hsub2(uint32_t a, uint32_t b) {
    uint32_t d;
    asm("sub.f16x2 %0, %1, %2;" : "=r"(d) : "r"(a), "r"(b));
    return d;
}
__device__ __forceinline__ uint32_t ex2h2(uint32_t a) {
    uint32_t d;
    asm("ex2.approx.f16x2 %0, %1;" : "=r"(d) : "r"(a));
    return d;
}
__device__ __forceinline__ void mma_f16(float d[4], const uint32_t a[4],
                                        const uint32_t* b, const float c[4]) {
    asm volatile(
        "mma.sync.aligned.m16n8k16.row.col.f32.f16.f16.f32 "
        "{%0,%1,%2,%3}, {%4,%5,%6,%7}, {%8,%9}, {%10,%11,%12,%13};"
        : "=f"(d[0]), "=f"(d[1]), "=f"(d[2]), "=f"(d[3])
        : "r"(a[0]), "r"(a[1]), "r"(a[2]), "r"(a[3]),
          "r"(b[0]), "r"(b[1]),
          "f"(c[0]), "f"(c[1]), "f"(c[2]), "f"(c[3]));
}
__device__ __forceinline__ void ldsm_x4(uint32_t r[4], uint32_t addr) {
    asm volatile("ldmatrix.sync.aligned.m8n8.x4.shared.b16 {%0,%1,%2,%3}, [%4];"
        : "=r"(r[0]), "=r"(r[1]), "=r"(r[2]), "=r"(r[3]) : "r"(addr));
}
__device__ __forceinline__ void ldsm_x4_t(uint32_t r[4], uint32_t addr) {
    asm volatile("ldmatrix.sync.aligned.m8n8.x4.trans.shared.b16 {%0,%1,%2,%3}, [%4];"
        : "=r"(r[0]), "=r"(r[1]), "=r"(r[2]), "=r"(r[3]) : "r"(addr));
}
__device__ __forceinline__ void cp_async16(uint32_t saddr, const void* gaddr) {
    asm volatile("cp.async.cg.shared.global [%0], [%1], 16;"
        :: "r"(saddr), "l"(gaddr) : "memory");
}

// ---------------------------------------------------------------------------
// Kernel 0: single fused fp32 -> fp16 convert.
// grid (DD*DD/4/256, 8): y in [0,3] = Wq/Wk/Wv/Wo; y in [4,7] = quarters of x.
// ---------------------------------------------------------------------------
__global__ __launch_bounds__(256) void cvt_all_kernel(
    const float4* __restrict__ x,
    const float4* __restrict__ w0, const float4* __restrict__ w1,
    const float4* __restrict__ w2, const float4* __restrict__ w3,
    uint2* __restrict__ dx,
    uint2* __restrict__ d0, uint2* __restrict__ d1,
    uint2* __restrict__ d2, uint2* __restrict__ d3)
{
    const int nseg = DD*DD/4;   // elements (float4) per segment
    const int i = blockIdx.x * 256 + threadIdx.x;   // < nseg
    const int y = blockIdx.y;
    const float4* s;
    uint2* d;
    if (y < 4) {
        s = (y == 0) ? w0 : (y == 1) ? w1 : (y == 2) ? w2 : w3;
        d = (y == 0) ? d0 : (y == 1) ? d1 : (y == 2) ? d2 : d3;
    } else {
        const int off = (y - 4) * nseg;
        s = x + off;
        d = dx + off;
    }
    const float4 v = s[i];
    uint2 o;
    o.x = f2h2(v.x, v.y);
    o.y = f2h2(v.z, v.w);
    d[i] = o;
}

// ---------------------------------------------------------------------------
// fp16 GEMM core (round-10 proven config): C(128x256) = A @ B^T, K=1024.
// 256 thr = 8 warps (2x4), warp tile 64x64, BK=32, 4-stage cp.async.
// Smem/stage 24KB: A 128x32h at +0 (8KB), B 256x32h at +8192 (16KB).
// Swizzle: byte = row*64 + ((ch ^ ((row>>1)&3))*16), ch = k>>3.
// ---------------------------------------------------------------------------
#define GSTG 24576u

__device__ __forceinline__ void gemm16_stage(
    const __half* __restrict__ A, const __half* __restrict__ B,
    int m0, int n0, uint32_t sbase, int s, int k0, int tid)
{
    const uint32_t sb = sbase + (uint32_t)s*GSTG;
    #pragma unroll
    for (int j = 0; j < 2; j++) {
        const int id  = tid + j*256;
        const int row = id >> 2;
        const int ch  = id & 3;
        const uint32_t sw = (uint32_t)(row*64 + ((ch ^ ((row>>1)&3))*16));
        cp_async16(sb + sw, A + (size_t)(m0 + row)*DD + k0 + ch*8);
    }
    #pragma unroll
    for (int j = 0; j < 4; j++) {
        const int id  = tid + j*256;
        const int row = id >> 2;
        const int ch  = id & 3;
        const uint32_t sw = (uint32_t)(row*64 + ((ch ^ ((row>>1)&3))*16));
        cp_async16(sb + 8192u + sw, B + (size_t)(n0 + row)*DD + k0 + ch*8);
    }
    asm volatile("cp.async.commit_group;" ::: "memory");
}

__device__ __forceinline__ void gemm16_core(
    const __half* __restrict__ A, const __half* __restrict__ B,
    int m0, int n0, uint32_t sbase, float acc[4][8][4])
{
    const int tid  = threadIdx.x;
    const int lane = tid & 31;
    const int warp = tid >> 5;
    const int wm = warp >> 2;        // 0..1 (64 m-rows)
    const int wn = warp & 3;         // 0..3 (64 n-cols)

    const int a_row_off = (lane & 7) + ((lane >> 3) & 1) * 8;
    const int a_ch_off  = lane >> 4;
    const int b_row_off = ((lane >> 4) << 3) + (lane & 7);
    const int b_ch_off  = (lane >> 3) & 1;

    gemm16_stage(A, B, m0, n0, sbase, 0, 0,  tid);
    gemm16_stage(A, B, m0, n0, sbase, 1, 32, tid);
    gemm16_stage(A, B, m0, n0, sbase, 2, 64, tid);

    for (int i = 0; i < 32; i++) {
        if (i < 30)       { asm volatile("cp.async.wait_group 2;" ::: "memory"); }
        else if (i == 30) { asm volatile("cp.async.wait_group 1;" ::: "memory"); }
        else              { asm volatile("cp.async.wait_group 0;" ::: "memory"); }
        __syncthreads();

        if (i + 3 < 32)
            gemm16_stage(A, B, m0, n0, sbase, (i+3) & 3, (i+3)*32, tid);

        const uint32_t sA = sbase + (uint32_t)(i & 3)*GSTG;
        const uint32_t sB = sA + 8192u;

        #pragma unroll
        for (int ks = 0; ks < 2; ks++) {
            uint32_t af[4][4];
            #pragma unroll
            for (int mt = 0; mt < 4; mt++) {
                const int row = wm*64 + mt*16 + a_row_off;
                const int ch  = 2*ks + a_ch_off;
                ldsm_x4(af[mt], sA + (uint32_t)(row*64 + ((ch ^ ((row>>1)&3))*16)));
            }
            uint32_t bf[8][2];
            #pragma unroll
            for (int pr = 0; pr < 4; pr++) {
                const int row = wn*64 + pr*16 + b_row_off;
                const int ch  = 2*ks + b_ch_off;
                uint32_t t[4];
                ldsm_x4(t, sB + (uint32_t)(row*64 + ((ch ^ ((row>>1)&3))*16)));
                bf[pr*2  ][0] = t[0]; bf[pr*2  ][1] = t[1];
                bf[pr*2+1][0] = t[2]; bf[pr*2+1][1] = t[3];
            }
            #pragma unroll
            for (int mt = 0; mt < 4; mt++)
                #pragma unroll
                for (int nt = 0; nt < 8; nt++)
                    mma_f16(acc[mt][nt], af[mt], bf[nt], acc[mt][nt]);
        }
    }
}

// ---------------------------------------------------------------------------
// Kernel 1: fused QKV projection. grid (4, 32, 3), block 256. fp16 in/out.
// ---------------------------------------------------------------------------
#define QSCALE 0.1803368801111743f   // 0.125 * log2(e)

__global__ __launch_bounds__(256) void qkv_gemm_kernel()
{
    extern __shared__ char smg[];
    const uint32_t sbase = smem_u32(smg);

    const __half* W   = (blockIdx.z == 0) ? g_wq16 : (blockIdx.z == 1) ? g_wk16 : g_wv16;
    __half*       out = (blockIdx.z == 0) ? g_q    : (blockIdx.z == 1) ? g_k    : g_v;
    const float oscale = (blockIdx.z == 0) ? QSCALE : 1.0f;

    const int m0 = blockIdx.y * 128;
    const int n0 = blockIdx.x * 256;

    float acc[4][8][4];
    #pragma unroll
    for (int i = 0; i < 4; i++)
        #pragma unroll
        for (int j = 0; j < 8; j++)
            #pragma unroll
            for (int k = 0; k < 4; k++) acc[i][j][k] = 0.f;

    gemm16_core(g_x16, W, m0, n0, sbase, acc);

    const int lane = threadIdx.x & 31;
    const int warp = threadIdx.x >> 5;
    const int wm = warp >> 2, wn = warp & 3;
    const int r = lane >> 2, c = lane & 3;

    #pragma unroll
    for (int mt = 0; mt < 4; mt++) {
        #pragma unroll
        for (int nt = 0; nt < 8; nt++) {
            #pragma unroll
            for (int half = 0; half < 2; half++) {
                const int m = m0 + wm*64 + mt*16 + r + half*8;
                const int b = m >> 11;
                const int s = m & 2047;
                const int n = n0 + wn*64 + nt*8 + c*2;
                const int h = n >> 6;
                const int d = n & 63;
                const uint32_t v = f2h2(acc[mt][nt][half*2+0]*oscale,
                                        acc[mt][nt][half*2+1]*oscale);
                *reinterpret_cast<uint32_t*>(
                    out + (((size_t)(b*NH + h))*SS + s)*HDIM + d) = v;
            }
        }
    }
}

// ---------------------------------------------------------------------------
// Kernel 3: output projection + bias. grid (4, 32), block 256.
// ---------------------------------------------------------------------------
__global__ __launch_bounds__(256) void oproj_kernel(
    const float* __restrict__ bo,
    float* __restrict__ out)
{
    extern __shared__ char smg[];
    const uint32_t sbase = smem_u32(smg);

    const int m0 = blockIdx.y * 128;
    const int n0 = blockIdx.x * 256;

    float acc[4][8][4];
    #pragma unroll
    for (int i = 0; i < 4; i++)
        #pragma unroll
        for (int j = 0; j < 8; j++)
            #pragma unroll
            for (int k = 0; k < 4; k++) acc[i][j][k] = 0.f;

    gemm16_core(g_ctx, g_wo16, m0, n0, sbase, acc);

    const int lane = threadIdx.x & 31;
    const int warp = threadIdx.x >> 5;
    const int wm = warp >> 2, wn = warp & 3;
    const int r = lane >> 2, c = lane & 3;

    #pragma unroll
    for (int mt = 0; mt < 4; mt++) {
        #pragma unroll
        for (int nt = 0; nt < 8; nt++) {
            #pragma unroll
            for (int half = 0; half < 2; half++) {
                const int m = m0 + wm*64 + mt*16 + r + half*8;
                const int n = n0 + wn*64 + nt*8 + c*2;
                float* o = out + (size_t)m*DD + n;
                o[0] = acc[mt][nt][half*2 + 0] + bo[n];
                o[1] = acc[mt][nt][half*2 + 1] + bo[n + 1];
            }
        }
    }
}

// ---------------------------------------------------------------------------
// Kernel 2: causal flash attention (round-13 proven config; grid transposed
// to (bh, qt) so heavy q-tiles occupy the lowest linear block IDs).
// log2 softmax, packed fp16 exp, l via P@ones mma, rescale skip,
// 2-stage KV cp.async pipeline. grid (32, 16), block 256.
// ---------------------------------------------------------------------------
#define ASTG 16384u

__global__ __launch_bounds__(256, 2) void attn_kernel()
{
    __shared__ __align__(16) char smA[2*ASTG];
    const uint32_t sbase = smem_u32(smA);

    const int tid  = threadIdx.x;
    const int lane = tid & 31;
    const int warp = tid >> 5;
    const int r = lane >> 2;
    const int c = lane & 3;
    const int qt = 15 - blockIdx.y;      // heavy q-tiles at lowest linear IDs
    const int bh = blockIdx.x;

    const __half* Qg = g_q + (size_t)bh * SS * HDIM;
    const __half* Kg = g_k + (size_t)bh * SS * HDIM;
    const __half* Vg = g_v + (size_t)bh * SS * HDIM;
    const uint32_t* Qg2 = reinterpret_cast<const uint32_t*>(Qg);
    const int q0 = qt * 128;
    const int qbase = q0 + warp * 16;

    // Q fragments (g_q pre-scaled by 0.125*log2e)
    uint32_t qf[4][4];
    #pragma unroll
    for (int kk = 0; kk < 4; kk++) {
        qf[kk][0] = Qg2[(size_t)(qbase + r    )*32 + kk*8 + c    ];
        qf[kk][1] = Qg2[(size_t)(qbase + r + 8)*32 + kk*8 + c    ];
        qf[kk][2] = Qg2[(size_t)(qbase + r    )*32 + kk*8 + c + 4];
        qf[kk][3] = Qg2[(size_t)(qbase + r + 8)*32 + kk*8 + c + 4];
    }

    const int k_key_off = ((lane >> 4) & 1) * 8 + (lane & 7);
    const int k_ch_off  = (lane >> 3) & 1;
    const int v_key_off = ((lane >> 3) & 1) * 8 + (lane & 7);
    const int v_ch_off  = (lane >> 4);

    const uint32_t ones2[2] = { 0x3C003C00u, 0x3C003C00u };  // fp16 1.0 x2

    float of[8][4];
    #pragma unroll
    for (int nt = 0; nt < 8; nt++)
        #pragma unroll
        for (int j = 0; j < 4; j++) of[nt][j] = 0.f;
    float lc[4] = {0.f, 0.f, 0.f, 0.f};   // row-sum accumulator (P @ ones)
    float m0i = -1e30f, m1i = -1e30f;

    auto stage = [&](int kt, int s) {
        const uint32_t sb = sbase + (uint32_t)s * ASTG;
        #pragma unroll
        for (int j = 0; j < 2; j++) {
            const int id  = tid + j*256;
            const int row = id >> 3;
            const int ch  = id & 7;
            const uint32_t sw = (uint32_t)(row*128 + ((ch ^ (row & 7))*16));
            cp_async16(sb + sw,          Kg + (size_t)(kt*64 + row)*HDIM + ch*8);
            cp_async16(sb + 8192u + sw,  Vg + (size_t)(kt*64 + row)*HDIM + ch*8);
        }
        asm volatile("cp.async.commit_group;" ::: "memory");
    };

    const int ktmax = 2*qt + 1;
    stage(0, 0);

    for (int kt = 0; kt <= ktmax; kt++) {
        asm volatile("cp.async.wait_group 0;" ::: "memory");
        __syncthreads();
        if (kt < ktmax) stage(kt + 1, (kt + 1) & 1);

        if (kt*64 > qbase + 15) continue;

        const uint32_t sK = sbase + (uint32_t)(kt & 1) * ASTG;
        const uint32_t sV = sK + 8192u;

        // ---- S = Q @ K^T (log2 domain) ----
        float sf[8][4];
        #pragma unroll
        for (int nt = 0; nt < 8; nt++)
            #pragma unroll
            for (int j = 0; j < 4; j++) sf[nt][j] = 0.f;

        #pragma unroll
        for (int kk = 0; kk < 4; kk++) {
            #pragma unroll
            for (int ntp = 0; ntp < 4; ntp++) {
                const int key = ntp*16 + k_key_off;
                const int ch  = 2*kk + k_ch_off;
                uint32_t t[4];
                ldsm_x4(t, sK + (uint32_t)(key*128 + ((ch ^ (key & 7))*16)));
                mma_f16(sf[2*ntp    ], qf[kk], &t[0], sf[2*ntp    ]);
                mma_f16(sf[2*ntp + 1], qf[kk], &t[2], sf[2*ntp + 1]);
            }
        }

        // ---- causal mask (boundary tiles only) ----
        const int qg0 = qbase + r;
        const int qg1 = qg0 + 8;
        if (kt*64 + 63 > qbase) {
            #pragma unroll
            for (int nt = 0; nt < 8; nt++) {
                const int col0 = kt*64 + nt*8 + c*2;
                if (col0     > qg0) sf[nt][0] = -1e30f;
                if (col0 + 1 > qg0) sf[nt][1] = -1e30f;
                if (col0     > qg1) sf[nt][2] = -1e30f;
                if (col0 + 1 > qg1) sf[nt][3] = -1e30f;
            }
        }

        // ---- online softmax (base-2, packed fp16 exp) ----
        float mx0 = -1e30f, mx1 = -1e30f;
        #pragma unroll
        for (int nt = 0; nt < 8; nt++) {
            mx0 = fmaxf(mx0, fmaxf(sf[nt][0], sf[nt][1]));
            mx1 = fmaxf(mx1, fmaxf(sf[nt][2], sf[nt][3]));
        }
        mx0 = fmaxf(mx0, __shfl_xor_sync(0xffffffffu, mx0, 1));
        mx0 = fmaxf(mx0, __shfl_xor_sync(0xffffffffu, mx0, 2));
        mx1 = fmaxf(mx1, __shfl_xor_sync(0xffffffffu, mx1, 1));
        mx1 = fmaxf(mx1, __shfl_xor_sync(0xffffffffu, mx1, 2));

        const float mn0 = fmaxf(m0i, mx0);
        const float mn1 = fmaxf(m1i, mx1);

        // packed exp: cvt pair -> HSUB2 broadcast max -> ex2.approx.f16x2
        const uint32_t mn0h2 = f2h2(mn0, mn0);
        const uint32_t mn1h2 = f2h2(mn1, mn1);
        uint32_t pk[4][4];
        #pragma unroll
        for (int nt = 0; nt < 8; nt++) {
            const uint32_t a = f2h2(sf[nt][0], sf[nt][1]);   // row0 pair
            const uint32_t b = f2h2(sf[nt][2], sf[nt][3]);   // row1 pair
            pk[nt >> 1][(nt & 1)*2    ] = ex2h2(hsub2(a, mn0h2));
            pk[nt >> 1][(nt & 1)*2 + 1] = ex2h2(hsub2(b, mn1h2));
        }

        // rescale accumulators only when a max moved (exact skip: cor==1)
        const bool chg = (mn0 > m0i) || (mn1 > m1i);
        if (__any_sync(0xffffffffu, chg)) {
            const float cor0 = exp2f(m0i - mn0);
            const float cor1 = exp2f(m1i - mn1);
            lc[0] *= cor0; lc[1] *= cor0; lc[2] *= cor1; lc[3] *= cor1;
            #pragma unroll
            for (int nt = 0; nt < 8; nt++) {
                of[nt][0] *= cor0;
                of[nt][1] *= cor0;
                of[nt][2] *= cor1;
                of[nt][3] *= cor1;
            }
        }
        m0i = mn0;
        m1i = mn1;

        // l += P @ ones (tensor pipe; lanes get their rows' sums in lc[0]/lc[2])
        #pragma unroll
        for (int kk = 0; kk < 4; kk++)
            mma_f16(lc, pk[kk], ones2, lc);

        // ---- O += P @ V ----
        #pragma unroll
        for (int kk = 0; kk < 4; kk++) {
            #pragma unroll
            for (int ntp = 0; ntp < 4; ntp++) {
                const int key = 16*kk + v_key_off;
                const int ch  = 2*ntp + v_ch_off;
                uint32_t t[4];
                ldsm_x4_t(t, sV + (uint32_t)(key*128 + ((ch ^ (key & 7))*16)));
                mma_f16(of[2*ntp    ], pk[kk], &t[0], of[2*ntp    ]);
                mma_f16(of[2*ntp + 1], pk[kk], &t[2], of[2*ntp + 1]);
            }
        }
    }

    // epilogue: normalize, write ctx (fp16) [b][s][h*64+d]
    const int b = bh >> 4, h = bh & 15;
    const float inv0 = 1.0f / lc[0];
    const float inv1 = 1.0f / lc[2];
    const int qg0 = qbase + r;
    #pragma unroll
    for (int nt = 0; nt < 8; nt++) {
        const int d = nt*8 + c*2;
        *reinterpret_cast<uint32_t*>(
            g_ctx + ((size_t)(b*SS + qg0    ))*DD + h*HDIM + d) = f2h2(of[nt][0]*inv0, of[nt][1]*inv0);
        *reinterpret_cast<uint32_t*>(
            g_ctx + ((size_t)(b*SS + qg0 + 8))*DD + h*HDIM + d) = f2h2(of[nt][2]*inv1, of[nt][3]*inv1);
    }
}

// ---------------------------------------------------------------------------
// Launch
// ---------------------------------------------------------------------------
extern "C" void kernel_launch(void* const* d_in, const int* in_sizes, int n_in,
                              void* d_out, int out_size)
{
    const float* x  = (const float*)d_in[0];
    const float* Wq = (const float*)d_in[1];
    const float* Wk = (const float*)d_in[2];
    const float* Wv = (const float*)d_in[3];
    const float* Wo = (const float*)d_in[4];
    const float* bo = (const float*)d_in[5];
    float* out = (float*)d_out;

    (void)in_sizes; (void)n_in; (void)out_size;

    __half* dx;  cudaGetSymbolAddress((void**)&dx,  g_x16);
    __half* dwq; cudaGetSymbolAddress((void**)&dwq, g_wq16);
    __half* dwk; cudaGetSymbolAddress((void**)&dwk, g_wk16);
    __half* dwv; cudaGetSymbolAddress((void**)&dwv, g_wv16);
    __half* dwo; cudaGetSymbolAddress((void**)&dwo, g_wo16);

    const int nseg = DD*DD/4;   // 256K float4 per segment
    cvt_all_kernel<<<dim3(nseg/256, 8), 256>>>(
        (const float4*)x,
        (const float4*)Wq, (const float4*)Wk, (const float4*)Wv, (const float4*)Wo,
        (uint2*)dx, (uint2*)dwq, (uint2*)dwk, (uint2*)dwv, (uint2*)dwo);

    const int gsm = 4 * GSTG;   // 98304 bytes dynamic smem (4-stage pipeline)
    cudaFuncSetAttribute(qkv_gemm_kernel,
                         cudaFuncAttributeMaxDynamicSharedMemorySize, gsm);
    cudaFuncSetAttribute(oproj_kernel,
                         cudaFuncAttributeMaxDynamicSharedMemorySize, gsm);

    qkv_gemm_kernel<<<dim3(4, 32, 3), 256, gsm>>>();
    attn_kernel<<<dim3(32, 16), 256>>>();
    oproj_kernel<<<dim3(4, 32), 256, gsm>>>(bo, out);
}

// round 16
// speedup vs baseline: 1.9265x; 1.0795x over previous
#include <cuda_runtime.h>
#include <cuda_fp16.h>
#include <math.h>
#include <stdint.h>

#define BB   2
#define SS   2048
#define DD   1024
#define NH   16
#define HDIM 64
#define NTOK (BB*SS)

// Scratch (device globals: allocation-free per harness rules)
__device__ __half g_q[NTOK*DD];    // [b][h][s][d], pre-scaled by 0.125*log2(e)
__device__ __half g_k[NTOK*DD];
__device__ __half g_v[NTOK*DD];
__device__ __half g_ctx[NTOK*DD];  // [b][s][h*64+d]
__device__ __half g_x16[NTOK*DD];  // fp16 copy of x
__device__ __half g_wq16[DD*DD];
__device__ __half g_wk16[DD*DD];
__device__ __half g_wv16[DD*DD];
__device__ __half g_wo16[DD*DD];

// ---------------------------------------------------------------------------
// Helpers
// ---------------------------------------------------------------------------
__device__ __forceinline__ uint32_t smem_u32(const void* p) {
    uint32_t a;
    asm("{ .reg .u64 t; cvta.to.shared.u64 t, %1; cvt.u32.u64 %0, t; }"
        : "=r"(a) : "l"(p));
    return a;
}
__device__ __forceinline__ uint32_t f2h2(float lo, float hi) {
    __half2 h = __floats2half2_rn(lo, hi);
    return *reinterpret_cast<uint32_t*>(&h);
}
__device__ __forceinline__ uint32_t hsub2(uint32_t a, uint32_t b) {
    uint32_t d;
    asm("sub.f16x2 %0, %1, %2;" : "=r"(d) : "r"(a), "r"(b));
    return d;
}
__device__ __forceinline__ uint32_t ex2h2(uint32_t a) {
    uint32_t d;
    asm("ex2.approx.f16x2 %0, %1;" : "=r"(d) : "r"(a));
    return d;
}
__device__ __forceinline__ void mma_f16(float d[4], const uint32_t a[4],
                                        const uint32_t* b, const float c[4]) {
    asm volatile(
        "mma.sync.aligned.m16n8k16.row.col.f32.f16.f16.f32 "
        "{%0,%1,%2,%3}, {%4,%5,%6,%7}, {%8,%9}, {%10,%11,%12,%13};"
        : "=f"(d[0]), "=f"(d[1]), "=f"(d[2]), "=f"(d[3])
        : "r"(a[0]), "r"(a[1]), "r"(a[2]), "r"(a[3]),
          "r"(b[0]), "r"(b[1]),
          "f"(c[0]), "f"(c[1]), "f"(c[2]), "f"(c[3]));
}
__device__ __forceinline__ void ldsm_x4(uint32_t r[4], uint32_t addr) {
    asm volatile("ldmatrix.sync.aligned.m8n8.x4.shared.b16 {%0,%1,%2,%3}, [%4];"
        : "=r"(r[0]), "=r"(r[1]), "=r"(r[2]), "=r"(r[3]) : "r"(addr));
}
__device__ __forceinline__ void ldsm_x4_t(uint32_t r[4], uint32_t addr) {
    asm volatile("ldmatrix.sync.aligned.m8n8.x4.trans.shared.b16 {%0,%1,%2,%3}, [%4];"
        : "=r"(r[0]), "=r"(r[1]), "=r"(r[2]), "=r"(r[3]) : "r"(addr));
}
__device__ __forceinline__ void cp_async16(uint32_t saddr, const void* gaddr) {
    asm volatile("cp.async.cg.shared.global [%0], [%1], 16;"
        :: "r"(saddr), "l"(gaddr) : "memory");
}

// ---------------------------------------------------------------------------
// Kernel 0: single fused fp32 -> fp16 convert.
// grid (DD*DD/4/256, 8): y in [0,3] = Wq/Wk/Wv/Wo; y in [4,7] = quarters of x.
// ---------------------------------------------------------------------------
__global__ __launch_bounds__(256) void cvt_all_kernel(
    const float4* __restrict__ x,
    const float4* __restrict__ w0, const float4* __restrict__ w1,
    const float4* __restrict__ w2, const float4* __restrict__ w3,
    uint2* __restrict__ dx,
    uint2* __restrict__ d0, uint2* __restrict__ d1,
    uint2* __restrict__ d2, uint2* __restrict__ d3)
{
    const int nseg = DD*DD/4;   // elements (float4) per segment
    const int i = blockIdx.x * 256 + threadIdx.x;   // < nseg
    const int y = blockIdx.y;
    const float4* s;
    uint2* d;
    if (y < 4) {
        s = (y == 0) ? w0 : (y == 1) ? w1 : (y == 2) ? w2 : w3;
        d = (y == 0) ? d0 : (y == 1) ? d1 : (y == 2) ? d2 : d3;
    } else {
        const int off = (y - 4) * nseg;
        s = x + off;
        d = dx + off;
    }
    const float4 v = s[i];
    uint2 o;
    o.x = f2h2(v.x, v.y);
    o.y = f2h2(v.z, v.w);
    d[i] = o;
}

// ---------------------------------------------------------------------------
// fp16 GEMM core: C(128x256) = A @ B^T, K=1024.
// 256 thr = 8 warps (2x4), warp tile 64x64, BK=64, 3-stage cp.async.
// Smem/stage 48KB: A 128x64h at +0 (16KB, 128B rows), B 256x64h at +16384.
// Swizzle (128B rows): byte = row*128 + ((ch ^ (row&7))*16), ch = k>>3.
// 16 mainloop iterations -> half the barrier count of the BK=32 version.
// ---------------------------------------------------------------------------
#define GSTG 49152u

__device__ __forceinline__ void gemm16_stage(
    const __half* __restrict__ A, const __half* __restrict__ B,
    int m0, int n0, uint32_t sbase, int s, int k0, int tid)
{
    const uint32_t sb = sbase + (uint32_t)s*GSTG;
    #pragma unroll
    for (int j = 0; j < 4; j++) {
        const int id  = tid + j*256;
        const int row = id >> 3;         // 0..127
        const int ch  = id & 7;
        const uint32_t sw = (uint32_t)(row*128 + ((ch ^ (row & 7))*16));
        cp_async16(sb + sw, A + (size_t)(m0 + row)*DD + k0 + ch*8);
    }
    #pragma unroll
    for (int j = 0; j < 8; j++) {
        const int id  = tid + j*256;
        const int row = id >> 3;         // 0..255
        const int ch  = id & 7;
        const uint32_t sw = (uint32_t)(row*128 + ((ch ^ (row & 7))*16));
        cp_async16(sb + 16384u + sw, B + (size_t)(n0 + row)*DD + k0 + ch*8);
    }
    asm volatile("cp.async.commit_group;" ::: "memory");
}

__device__ __forceinline__ void gemm16_core(
    const __half* __restrict__ A, const __half* __restrict__ B,
    int m0, int n0, uint32_t sbase, float acc[4][8][4])
{
    const int tid  = threadIdx.x;
    const int lane = tid & 31;
    const int warp = tid >> 5;
    const int wm = warp >> 2;        // 0..1 (64 m-rows)
    const int wn = warp & 3;         // 0..3 (64 n-cols)

    const int a_row_off = (lane & 7) + ((lane >> 3) & 1) * 8;
    const int a_ch_off  = lane >> 4;
    const int b_row_off = ((lane >> 4) << 3) + (lane & 7);
    const int b_ch_off  = (lane >> 3) & 1;

    gemm16_stage(A, B, m0, n0, sbase, 0, 0,  tid);
    gemm16_stage(A, B, m0, n0, sbase, 1, 64, tid);

    for (int i = 0; i < 16; i++) {
        if (i < 15) { asm volatile("cp.async.wait_group 1;" ::: "memory"); }
        else        { asm volatile("cp.async.wait_group 0;" ::: "memory"); }
        __syncthreads();

        if (i + 2 < 16) {
            const int s2 = (i+2) - ((i+2)/3)*3;
            gemm16_stage(A, B, m0, n0, sbase, s2, (i+2)*64, tid);
        }

        const int sbuf = i - (i/3)*3;
        const uint32_t sA = sbase + (uint32_t)sbuf*GSTG;
        const uint32_t sB = sA + 16384u;

        #pragma unroll
        for (int ks = 0; ks < 4; ks++) {
            uint32_t af[4][4];
            #pragma unroll
            for (int mt = 0; mt < 4; mt++) {
                const int row = wm*64 + mt*16 + a_row_off;
                const int ch  = 2*ks + a_ch_off;
                ldsm_x4(af[mt], sA + (uint32_t)(row*128 + ((ch ^ (row & 7))*16)));
            }
            uint32_t bf[8][2];
            #pragma unroll
            for (int pr = 0; pr < 4; pr++) {
                const int row = wn*64 + pr*16 + b_row_off;
                const int ch  = 2*ks + b_ch_off;
                uint32_t t[4];
                ldsm_x4(t, sB + (uint32_t)(row*128 + ((ch ^ (row & 7))*16)));
                bf[pr*2  ][0] = t[0]; bf[pr*2  ][1] = t[1];
                bf[pr*2+1][0] = t[2]; bf[pr*2+1][1] = t[3];
            }
            #pragma unroll
            for (int mt = 0; mt < 4; mt++)
                #pragma unroll
                for (int nt = 0; nt < 8; nt++)
                    mma_f16(acc[mt][nt], af[mt], bf[nt], acc[mt][nt]);
        }
    }
}

// ---------------------------------------------------------------------------
// Kernel 1: fused QKV projection. grid (4, 32, 3), block 256. fp16 in/out.
// ---------------------------------------------------------------------------
#define QSCALE 0.1803368801111743f   // 0.125 * log2(e)

__global__ __launch_bounds__(256) void qkv_gemm_kernel()
{
    extern __shared__ char smg[];
    const uint32_t sbase = smem_u32(smg);

    const __half* W   = (blockIdx.z == 0) ? g_wq16 : (blockIdx.z == 1) ? g_wk16 : g_wv16;
    __half*       out = (blockIdx.z == 0) ? g_q    : (blockIdx.z == 1) ? g_k    : g_v;
    const float oscale = (blockIdx.z == 0) ? QSCALE : 1.0f;

    const int m0 = blockIdx.y * 128;
    const int n0 = blockIdx.x * 256;

    float acc[4][8][4];
    #pragma unroll
    for (int i = 0; i < 4; i++)
        #pragma unroll
        for (int j = 0; j < 8; j++)
            #pragma unroll
            for (int k = 0; k < 4; k++) acc[i][j][k] = 0.f;

    gemm16_core(g_x16, W, m0, n0, sbase, acc);

    const int lane = threadIdx.x & 31;
    const int warp = threadIdx.x >> 5;
    const int wm = warp >> 2, wn = warp & 3;
    const int r = lane >> 2, c = lane & 3;

    #pragma unroll
    for (int mt = 0; mt < 4; mt++) {
        #pragma unroll
        for (int nt = 0; nt < 8; nt++) {
            #pragma unroll
            for (int half = 0; half < 2; half++) {
                const int m = m0 + wm*64 + mt*16 + r + half*8;
                const int b = m >> 11;
                const int s = m & 2047;
                const int n = n0 + wn*64 + nt*8 + c*2;
                const int h = n >> 6;
                const int d = n & 63;
                const uint32_t v = f2h2(acc[mt][nt][half*2+0]*oscale,
                                        acc[mt][nt][half*2+1]*oscale);
                *reinterpret_cast<uint32_t*>(
                    out + (((size_t)(b*NH + h))*SS + s)*HDIM + d) = v;
            }
        }
    }
}

// ---------------------------------------------------------------------------
// Kernel 3: output projection + bias. grid (4, 32), block 256.
// ---------------------------------------------------------------------------
__global__ __launch_bounds__(256) void oproj_kernel(
    const float* __restrict__ bo,
    float* __restrict__ out)
{
    extern __shared__ char smg[];
    const uint32_t sbase = smem_u32(smg);

    const int m0 = blockIdx.y * 128;
    const int n0 = blockIdx.x * 256;

    float acc[4][8][4];
    #pragma unroll
    for (int i = 0; i < 4; i++)
        #pragma unroll
        for (int j = 0; j < 8; j++)
            #pragma unroll
            for (int k = 0; k < 4; k++) acc[i][j][k] = 0.f;

    gemm16_core(g_ctx, g_wo16, m0, n0, sbase, acc);

    const int lane = threadIdx.x & 31;
    const int warp = threadIdx.x >> 5;
    const int wm = warp >> 2, wn = warp & 3;
    const int r = lane >> 2, c = lane & 3;

    #pragma unroll
    for (int mt = 0; mt < 4; mt++) {
        #pragma unroll
        for (int nt = 0; nt < 8; nt++) {
            #pragma unroll
            for (int half = 0; half < 2; half++) {
                const int m = m0 + wm*64 + mt*16 + r + half*8;
                const int n = n0 + wn*64 + nt*8 + c*2;
                float* o = out + (size_t)m*DD + n;
                o[0] = acc[mt][nt][half*2 + 0] + bo[n];
                o[1] = acc[mt][nt][half*2 + 1] + bo[n + 1];
            }
        }
    }
}

// ---------------------------------------------------------------------------
// Kernel 2: causal flash attention (round-15 winning config, verbatim).
// grid (32, 16): x = bh, y -> qt = 15 - y (heavy q-tiles first). block 256.
// ---------------------------------------------------------------------------
#define ASTG 16384u

__global__ __launch_bounds__(256, 2) void attn_kernel()
{
    __shared__ __align__(16) char smA[2*ASTG];
    const uint32_t sbase = smem_u32(smA);

    const int tid  = threadIdx.x;
    const int lane = tid & 31;
    const int warp = tid >> 5;
    const int r = lane >> 2;
    const int c = lane & 3;
    const int qt = 15 - blockIdx.y;      // heavy q-tiles at lowest linear IDs
    const int bh = blockIdx.x;

    const __half* Qg = g_q + (size_t)bh * SS * HDIM;
    const __half* Kg = g_k + (size_t)bh * SS * HDIM;
    const __half* Vg = g_v + (size_t)bh * SS * HDIM;
    const uint32_t* Qg2 = reinterpret_cast<const uint32_t*>(Qg);
    const int q0 = qt * 128;
    const int qbase = q0 + warp * 16;

    // Q fragments (g_q pre-scaled by 0.125*log2e)
    uint32_t qf[4][4];
    #pragma unroll
    for (int kk = 0; kk < 4; kk++) {
        qf[kk][0] = Qg2[(size_t)(qbase + r    )*32 + kk*8 + c    ];
        qf[kk][1] = Qg2[(size_t)(qbase + r + 8)*32 + kk*8 + c    ];
        qf[kk][2] = Qg2[(size_t)(qbase + r    )*32 + kk*8 + c + 4];
        qf[kk][3] = Qg2[(size_t)(qbase + r + 8)*32 + kk*8 + c + 4];
    }

    const int k_key_off = ((lane >> 4) & 1) * 8 + (lane & 7);
    const int k_ch_off  = (lane >> 3) & 1;
    const int v_key_off = ((lane >> 3) & 1) * 8 + (lane & 7);
    const int v_ch_off  = (lane >> 4);

    const uint32_t ones2[2] = { 0x3C003C00u, 0x3C003C00u };  // fp16 1.0 x2

    float of[8][4];
    #pragma unroll
    for (int nt = 0; nt < 8; nt++)
        #pragma unroll
        for (int j = 0; j < 4; j++) of[nt][j] = 0.f;
    float lc[4] = {0.f, 0.f, 0.f, 0.f};   // row-sum accumulator (P @ ones)
    float m0i = -1e30f, m1i = -1e30f;

    auto stage = [&](int kt, int s) {
        const uint32_t sb = sbase + (uint32_t)s * ASTG;
        #pragma unroll
        for (int j = 0; j < 2; j++) {
            const int id  = tid + j*256;
            const int row = id >> 3;
            const int ch  = id & 7;
            const uint32_t sw = (uint32_t)(row*128 + ((ch ^ (row & 7))*16));
            cp_async16(sb + sw,          Kg + (size_t)(kt*64 + row)*HDIM + ch*8);
            cp_async16(sb + 8192u + sw,  Vg + (size_t)(kt*64 + row)*HDIM + ch*8);
        }
        asm volatile("cp.async.commit_group;" ::: "memory");
    };

    const int ktmax = 2*qt + 1;
    stage(0, 0);

    for (int kt = 0; kt <= ktmax; kt++) {
        asm volatile("cp.async.wait_group 0;" ::: "memory");
        __syncthreads();
        if (kt < ktmax) stage(kt + 1, (kt + 1) & 1);

        if (kt*64 > qbase + 15) continue;

        const uint32_t sK = sbase + (uint32_t)(kt & 1) * ASTG;
        const uint32_t sV = sK + 8192u;

        // ---- S = Q @ K^T (log2 domain) ----
        float sf[8][4];
        #pragma unroll
        for (int nt = 0; nt < 8; nt++)
            #pragma unroll
            for (int j = 0; j < 4; j++) sf[nt][j] = 0.f;

        #pragma unroll
        for (int kk = 0; kk < 4; kk++) {
            #pragma unroll
            for (int ntp = 0; ntp < 4; ntp++) {
                const int key = ntp*16 + k_key_off;
                const int ch  = 2*kk + k_ch_off;
                uint32_t t[4];
                ldsm_x4(t, sK + (uint32_t)(key*128 + ((ch ^ (key & 7))*16)));
                mma_f16(sf[2*ntp    ], qf[kk], &t[0], sf[2*ntp    ]);
                mma_f16(sf[2*ntp + 1], qf[kk], &t[2], sf[2*ntp + 1]);
            }
        }

        // ---- causal mask (boundary tiles only) ----
        const int qg0 = qbase + r;
        const int qg1 = qg0 + 8;
        if (kt*64 + 63 > qbase) {
            #pragma unroll
            for (int nt = 0; nt < 8; nt++) {
                const int col0 = kt*64 + nt*8 + c*2;
                if (col0     > qg0) sf[nt][0] = -1e30f;
                if (col0 + 1 > qg0) sf[nt][1] = -1e30f;
                if (col0     > qg1) sf[nt][2] = -1e30f;
                if (col0 + 1 > qg1) sf[nt][3] = -1e30f;
            }
        }

        // ---- online softmax (base-2, packed fp16 exp) ----
        float mx0 = -1e30f, mx1 = -1e30f;
        #pragma unroll
        for (int nt = 0; nt < 8; nt++) {
            mx0 = fmaxf(mx0, fmaxf(sf[nt][0], sf[nt][1]));
            mx1 = fmaxf(mx1, fmaxf(sf[nt][2], sf[nt][3]));
        }
        mx0 = fmaxf(mx0, __shfl_xor_sync(0xffffffffu, mx0, 1));
        mx0 = fmaxf(mx0, __shfl_xor_sync(0xffffffffu, mx0, 2));
        mx1 = fmaxf(mx1, __shfl_xor_sync(0xffffffffu, mx1, 1));
        mx1 = fmaxf(mx1, __shfl_xor_sync(0xffffffffu, mx1, 2));

        const float mn0 = fmaxf(m0i, mx0);
        const float mn1 = fmaxf(m1i, mx1);

        // packed exp: cvt pair -> HSUB2 broadcast max -> ex2.approx.f16x2
        const uint32_t mn0h2 = f2h2(mn0, mn0);
        const uint32_t mn1h2 = f2h2(mn1, mn1);
        uint32_t pk[4][4];
        #pragma unroll
        for (int nt = 0; nt < 8; nt++) {
            const uint32_t a = f2h2(sf[nt][0], sf[nt][1]);   // row0 pair
            const uint32_t b = f2h2(sf[nt][2], sf[nt][3]);   // row1 pair
            pk[nt >> 1][(nt & 1)*2    ] = ex2h2(hsub2(a, mn0h2));
            pk[nt >> 1][(nt & 1)*2 + 1] = ex2h2(hsub2(b, mn1h2));
        }

        // rescale accumulators only when a max moved (exact skip: cor==1)
        const bool chg = (mn0 > m0i) || (mn1 > m1i);
        if (__any_sync(0xffffffffu, chg)) {
            const float cor0 = exp2f(m0i - mn0);
            const float cor1 = exp2f(m1i - mn1);
            lc[0] *= cor0; lc[1] *= cor0; lc[2] *= cor1; lc[3] *= cor1;
            #pragma unroll
            for (int nt = 0; nt < 8; nt++) {
                of[nt][0] *= cor0;
                of[nt][1] *= cor0;
                of[nt][2] *= cor1;
                of[nt][3] *= cor1;
            }
        }
        m0i = mn0;
        m1i = mn1;

        // l += P @ ones (tensor pipe; lanes get their rows' sums in lc[0]/lc[2])
        #pragma unroll
        for (int kk = 0; kk < 4; kk++)
            mma_f16(lc, pk[kk], ones2, lc);

        // ---- O += P @ V ----
        #pragma unroll
        for (int kk = 0; kk < 4; kk++) {
            #pragma unroll
            for (int ntp = 0; ntp < 4; ntp++) {
                const int key = 16*kk + v_key_off;
                const int ch  = 2*ntp + v_ch_off;
                uint32_t t[4];
                ldsm_x4_t(t, sV + (uint32_t)(key*128 + ((ch ^ (key & 7))*16)));
                mma_f16(of[2*ntp    ], pk[kk], &t[0], of[2*ntp    ]);
                mma_f16(of[2*ntp + 1], pk[kk], &t[2], of[2*ntp + 1]);
            }
        }
    }

    // epilogue: normalize, write ctx (fp16) [b][s][h*64+d]
    const int b = bh >> 4, h = bh & 15;
    const float inv0 = 1.0f / lc[0];
    const float inv1 = 1.0f / lc[2];
    const int qg0 = qbase + r;
    #pragma unroll
    for (int nt = 0; nt < 8; nt++) {
        const int d = nt*8 + c*2;
        *reinterpret_cast<uint32_t*>(
            g_ctx + ((size_t)(b*SS + qg0    ))*DD + h*HDIM + d) = f2h2(of[nt][0]*inv0, of[nt][1]*inv0);
        *reinterpret_cast<uint32_t*>(
            g_ctx + ((size_t)(b*SS + qg0 + 8))*DD + h*HDIM + d) = f2h2(of[nt][2]*inv1, of[nt][3]*inv1);
    }
}

// ---------------------------------------------------------------------------
// Launch
// ---------------------------------------------------------------------------
extern "C" void kernel_launch(void* const* d_in, const int* in_sizes, int n_in,
                              void* d_out, int out_size)
{
    const float* x  = (const float*)d_in[0];
    const float* Wq = (const float*)d_in[1];
    const float* Wk = (const float*)d_in[2];
    const float* Wv = (const float*)d_in[3];
    const float* Wo = (const float*)d_in[4];
    const float* bo = (const float*)d_in[5];
    float* out = (float*)d_out;

    (void)in_sizes; (void)n_in; (void)out_size;

    __half* dx;  cudaGetSymbolAddress((void**)&dx,  g_x16);
    __half* dwq; cudaGetSymbolAddress((void**)&dwq, g_wq16);
    __half* dwk; cudaGetSymbolAddress((void**)&dwk, g_wk16);
    __half* dwv; cudaGetSymbolAddress((void**)&dwv, g_wv16);
    __half* dwo; cudaGetSymbolAddress((void**)&dwo, g_wo16);

    const int nseg = DD*DD/4;   // 256K float4 per segment
    cvt_all_kernel<<<dim3(nseg/256, 8), 256>>>(
        (const float4*)x,
        (const float4*)Wq, (const float4*)Wk, (const float4*)Wv, (const float4*)Wo,
        (uint2*)dx, (uint2*)dwq, (uint2*)dwk, (uint2*)dwv, (uint2*)dwo);

    const int gsm = 3 * GSTG;   // 147456 bytes dynamic smem (3-stage BK=64)
    cudaFuncSetAttribute(qkv_gemm_kernel,
                         cudaFuncAttributeMaxDynamicSharedMemorySize, gsm);
    cudaFuncSetAttribute(oproj_kernel,
                         cudaFuncAttributeMaxDynamicSharedMemorySize, gsm);

    qkv_gemm_kernel<<<dim3(4, 32, 3), 256, gsm>>>();
    attn_kernel<<<dim3(32, 16), 256>>>();
    oproj_kernel<<<dim3(4, 32), 256, gsm>>>(bo, out);
}

// round 17
// speedup vs baseline: 1.9725x; 1.0238x over previous
#include <cuda_runtime.h>
#include <cuda_fp16.h>
#include <math.h>
#include <stdint.h>

#define BB   2
#define SS   2048
#define DD   1024
#define NH   16
#define HDIM 64
#define NTOK (BB*SS)

// Scratch (device globals: allocation-free per harness rules)
__device__ __half g_q[NTOK*DD];    // [b][h][s][d], pre-scaled by 0.125*log2(e)
__device__ __half g_k[NTOK*DD];
__device__ __half g_v[NTOK*DD];
__device__ __half g_ctx[NTOK*DD];  // [b][s][h*64+d]
__device__ __half g_x16[NTOK*DD];  // fp16 copy of x
__device__ __half g_wq16[DD*DD];
__device__ __half g_wk16[DD*DD];
__device__ __half g_wv16[DD*DD];
__device__ __half g_wo16[DD*DD];

// ---------------------------------------------------------------------------
// Helpers
// ---------------------------------------------------------------------------
__device__ __forceinline__ uint32_t smem_u32(const void* p) {
    uint32_t a;
    asm("{ .reg .u64 t; cvta.to.shared.u64 t, %1; cvt.u32.u64 %0, t; }"
        : "=r"(a) : "l"(p));
    return a;
}
__device__ __forceinline__ uint32_t f2h2(float lo, float hi) {
    __half2 h = __floats2half2_rn(lo, hi);
    return *reinterpret_cast<uint32_t*>(&h);
}
__device__ __forceinline__ uint32_t hsub2(uint32_t a, uint32_t b) {
    uint32_t d;
    asm("sub.f16x2 %0, %1, %2;" : "=r"(d) : "r"(a), "r"(b));
    return d;
}
__device__ __forceinline__ uint32_t ex2h2(uint32_t a) {
    uint32_t d;
    asm("ex2.approx.f16x2 %0, %1;" : "=r"(d) : "r"(a));
    return d;
}
__device__ __forceinline__ void mma_f16(float d[4], const uint32_t a[4],
                                        const uint32_t* b, const float c[4]) {
    asm volatile(
        "mma.sync.aligned.m16n8k16.row.col.f32.f16.f16.f32 "
        "{%0,%1,%2,%3}, {%4,%5,%6,%7}, {%8,%9}, {%10,%11,%12,%13};"
        : "=f"(d[0]), "=f"(d[1]), "=f"(d[2]), "=f"(d[3])
        : "r"(a[0]), "r"(a[1]), "r"(a[2]), "r"(a[3]),
          "r"(b[0]), "r"(b[1]),
          "f"(c[0]), "f"(c[1]), "f"(c[2]), "f"(c[3]));
}
__device__ __forceinline__ void ldsm_x4(uint32_t r[4], uint32_t addr) {
    asm volatile("ldmatrix.sync.aligned.m8n8.x4.shared.b16 {%0,%1,%2,%3}, [%4];"
        : "=r"(r[0]), "=r"(r[1]), "=r"(r[2]), "=r"(r[3]) : "r"(addr));
}
__device__ __forceinline__ void ldsm_x4_t(uint32_t r[4], uint32_t addr) {
    asm volatile("ldmatrix.sync.aligned.m8n8.x4.trans.shared.b16 {%0,%1,%2,%3}, [%4];"
        : "=r"(r[0]), "=r"(r[1]), "=r"(r[2]), "=r"(r[3]) : "r"(addr));
}
__device__ __forceinline__ void cp_async16(uint32_t saddr, const void* gaddr) {
    asm volatile("cp.async.cg.shared.global [%0], [%1], 16;"
        :: "r"(saddr), "l"(gaddr) : "memory");
}

// ---------------------------------------------------------------------------
// Kernel 0: single fused fp32 -> fp16 convert.
// grid (DD*DD/4/256, 8): y in [0,3] = Wq/Wk/Wv/Wo; y in [4,7] = quarters of x.
// ---------------------------------------------------------------------------
__global__ __launch_bounds__(256) void cvt_all_kernel(
    const float4* __restrict__ x,
    const float4* __restrict__ w0, const float4* __restrict__ w1,
    const float4* __restrict__ w2, const float4* __restrict__ w3,
    uint2* __restrict__ dx,
    uint2* __restrict__ d0, uint2* __restrict__ d1,
    uint2* __restrict__ d2, uint2* __restrict__ d3)
{
    const int nseg = DD*DD/4;   // elements (float4) per segment
    const int i = blockIdx.x * 256 + threadIdx.x;   // < nseg
    const int y = blockIdx.y;
    const float4* s;
    uint2* d;
    if (y < 4) {
        s = (y == 0) ? w0 : (y == 1) ? w1 : (y == 2) ? w2 : w3;
        d = (y == 0) ? d0 : (y == 1) ? d1 : (y == 2) ? d2 : d3;
    } else {
        const int off = (y - 4) * nseg;
        s = x + off;
        d = dx + off;
    }
    const float4 v = s[i];
    uint2 o;
    o.x = f2h2(v.x, v.y);
    o.y = f2h2(v.z, v.w);
    d[i] = o;
}

// ---------------------------------------------------------------------------
// fp16 GEMM core: C(128x256) = A @ B^T, K=1024.
// 256 thr = 8 warps (2x4), warp tile 64x64, BK=128, 2-stage cp.async.
// Smem/stage 96KB, two 64-k sub-blocks each with the proven 128B-row layout:
//   A sub-block 16KB at +ksub*16384; B sub-block 32KB at +32768+ksub*32768.
// Swizzle (128B rows): byte = row*128 + ((ch ^ (row&7))*16), ch = (k%64)>>3.
// 8 mainloop iterations -> half the barrier count of the BK=64 version.
// ---------------------------------------------------------------------------
#define GSTG 98304u

__device__ __forceinline__ void gemm16_stage(
    const __half* __restrict__ A, const __half* __restrict__ B,
    int m0, int n0, uint32_t sbase, int s, int k0, int tid)
{
    const uint32_t sb = sbase + (uint32_t)s*GSTG;
    #pragma unroll
    for (int ksub = 0; ksub < 2; ksub++) {
        const uint32_t aoff = sb + (uint32_t)(ksub*16384);
        const uint32_t boff = sb + 32768u + (uint32_t)(ksub*32768);
        const int kg = k0 + ksub*64;
        #pragma unroll
        for (int j = 0; j < 4; j++) {
            const int id  = tid + j*256;
            const int row = id >> 3;         // 0..127
            const int ch  = id & 7;
            const uint32_t sw = (uint32_t)(row*128 + ((ch ^ (row & 7))*16));
            cp_async16(aoff + sw, A + (size_t)(m0 + row)*DD + kg + ch*8);
        }
        #pragma unroll
        for (int j = 0; j < 8; j++) {
            const int id  = tid + j*256;
            const int row = id >> 3;         // 0..255
            const int ch  = id & 7;
            const uint32_t sw = (uint32_t)(row*128 + ((ch ^ (row & 7))*16));
            cp_async16(boff + sw, B + (size_t)(n0 + row)*DD + kg + ch*8);
        }
    }
    asm volatile("cp.async.commit_group;" ::: "memory");
}

__device__ __forceinline__ void gemm16_core(
    const __half* __restrict__ A, const __half* __restrict__ B,
    int m0, int n0, uint32_t sbase, float acc[4][8][4])
{
    const int tid  = threadIdx.x;
    const int lane = tid & 31;
    const int warp = tid >> 5;
    const int wm = warp >> 2;        // 0..1 (64 m-rows)
    const int wn = warp & 3;         // 0..3 (64 n-cols)

    const int a_row_off = (lane & 7) + ((lane >> 3) & 1) * 8;
    const int a_ch_off  = lane >> 4;
    const int b_row_off = ((lane >> 4) << 3) + (lane & 7);
    const int b_ch_off  = (lane >> 3) & 1;

    gemm16_stage(A, B, m0, n0, sbase, 0, 0, tid);

    for (int i = 0; i < 8; i++) {
        asm volatile("cp.async.wait_group 0;" ::: "memory");
        __syncthreads();

        if (i + 1 < 8)
            gemm16_stage(A, B, m0, n0, sbase, (i+1) & 1, (i+1)*128, tid);

        const uint32_t sA = sbase + (uint32_t)(i & 1)*GSTG;
        const uint32_t sB = sA + 32768u;

        #pragma unroll
        for (int ks = 0; ks < 8; ks++) {
            const int sub = ks >> 2;
            const int kw  = ks & 3;
            const uint32_t sAs = sA + (uint32_t)(sub*16384);
            const uint32_t sBs = sB + (uint32_t)(sub*32768);
            uint32_t af[4][4];
            #pragma unroll
            for (int mt = 0; mt < 4; mt++) {
                const int row = wm*64 + mt*16 + a_row_off;
                const int ch  = 2*kw + a_ch_off;
                ldsm_x4(af[mt], sAs + (uint32_t)(row*128 + ((ch ^ (row & 7))*16)));
            }
            uint32_t bf[8][2];
            #pragma unroll
            for (int pr = 0; pr < 4; pr++) {
                const int row = wn*64 + pr*16 + b_row_off;
                const int ch  = 2*kw + b_ch_off;
                uint32_t t[4];
                ldsm_x4(t, sBs + (uint32_t)(row*128 + ((ch ^ (row & 7))*16)));
                bf[pr*2  ][0] = t[0]; bf[pr*2  ][1] = t[1];
                bf[pr*2+1][0] = t[2]; bf[pr*2+1][1] = t[3];
            }
            #pragma unroll
            for (int mt = 0; mt < 4; mt++)
                #pragma unroll
                for (int nt = 0; nt < 8; nt++)
                    mma_f16(acc[mt][nt], af[mt], bf[nt], acc[mt][nt]);
        }
    }
}

// ---------------------------------------------------------------------------
// Kernel 1: fused QKV projection. grid (4, 32, 3), block 256. fp16 in/out.
// ---------------------------------------------------------------------------
#define QSCALE 0.1803368801111743f   // 0.125 * log2(e)

__global__ __launch_bounds__(256) void qkv_gemm_kernel()
{
    extern __shared__ char smg[];
    const uint32_t sbase = smem_u32(smg);

    const __half* W   = (blockIdx.z == 0) ? g_wq16 : (blockIdx.z == 1) ? g_wk16 : g_wv16;
    __half*       out = (blockIdx.z == 0) ? g_q    : (blockIdx.z == 1) ? g_k    : g_v;
    const float oscale = (blockIdx.z == 0) ? QSCALE : 1.0f;

    const int m0 = blockIdx.y * 128;
    const int n0 = blockIdx.x * 256;

    float acc[4][8][4];
    #pragma unroll
    for (int i = 0; i < 4; i++)
        #pragma unroll
        for (int j = 0; j < 8; j++)
            #pragma unroll
            for (int k = 0; k < 4; k++) acc[i][j][k] = 0.f;

    gemm16_core(g_x16, W, m0, n0, sbase, acc);

    const int lane = threadIdx.x & 31;
    const int warp = threadIdx.x >> 5;
    const int wm = warp >> 2, wn = warp & 3;
    const int r = lane >> 2, c = lane & 3;

    #pragma unroll
    for (int mt = 0; mt < 4; mt++) {
        #pragma unroll
        for (int nt = 0; nt < 8; nt++) {
            #pragma unroll
            for (int half = 0; half < 2; half++) {
                const int m = m0 + wm*64 + mt*16 + r + half*8;
                const int b = m >> 11;
                const int s = m & 2047;
                const int n = n0 + wn*64 + nt*8 + c*2;
                const int h = n >> 6;
                const int d = n & 63;
                const uint32_t v = f2h2(acc[mt][nt][half*2+0]*oscale,
                                        acc[mt][nt][half*2+1]*oscale);
                *reinterpret_cast<uint32_t*>(
                    out + (((size_t)(b*NH + h))*SS + s)*HDIM + d) = v;
            }
        }
    }
}

// ---------------------------------------------------------------------------
// Kernel 3: output projection + bias. grid (4, 32), block 256.
// ---------------------------------------------------------------------------
__global__ __launch_bounds__(256) void oproj_kernel(
    const float* __restrict__ bo,
    float* __restrict__ out)
{
    extern __shared__ char smg[];
    const uint32_t sbase = smem_u32(smg);

    const int m0 = blockIdx.y * 128;
    const int n0 = blockIdx.x * 256;

    float acc[4][8][4];
    #pragma unroll
    for (int i = 0; i < 4; i++)
        #pragma unroll
        for (int j = 0; j < 8; j++)
            #pragma unroll
            for (int k = 0; k < 4; k++) acc[i][j][k] = 0.f;

    gemm16_core(g_ctx, g_wo16, m0, n0, sbase, acc);

    const int lane = threadIdx.x & 31;
    const int warp = threadIdx.x >> 5;
    const int wm = warp >> 2, wn = warp & 3;
    const int r = lane >> 2, c = lane & 3;

    #pragma unroll
    for (int mt = 0; mt < 4; mt++) {
        #pragma unroll
        for (int nt = 0; nt < 8; nt++) {
            #pragma unroll
            for (int half = 0; half < 2; half++) {
                const int m = m0 + wm*64 + mt*16 + r + half*8;
                const int n = n0 + wn*64 + nt*8 + c*2;
                float* o = out + (size_t)m*DD + n;
                o[0] = acc[mt][nt][half*2 + 0] + bo[n];
                o[1] = acc[mt][nt][half*2 + 1] + bo[n + 1];
            }
        }
    }
}

// ---------------------------------------------------------------------------
// Kernel 2: causal flash attention (round-15 winning config, verbatim).
// grid (32, 16): x = bh, y -> qt = 15 - y (heavy q-tiles first). block 256.
// ---------------------------------------------------------------------------
#define ASTG 16384u

__global__ __launch_bounds__(256, 2) void attn_kernel()
{
    __shared__ __align__(16) char smA[2*ASTG];
    const uint32_t sbase = smem_u32(smA);

    const int tid  = threadIdx.x;
    const int lane = tid & 31;
    const int warp = tid >> 5;
    const int r = lane >> 2;
    const int c = lane & 3;
    const int qt = 15 - blockIdx.y;      // heavy q-tiles at lowest linear IDs
    const int bh = blockIdx.x;

    const __half* Qg = g_q + (size_t)bh * SS * HDIM;
    const __half* Kg = g_k + (size_t)bh * SS * HDIM;
    const __half* Vg = g_v + (size_t)bh * SS * HDIM;
    const uint32_t* Qg2 = reinterpret_cast<const uint32_t*>(Qg);
    const int q0 = qt * 128;
    const int qbase = q0 + warp * 16;

    // Q fragments (g_q pre-scaled by 0.125*log2e)
    uint32_t qf[4][4];
    #pragma unroll
    for (int kk = 0; kk < 4; kk++) {
        qf[kk][0] = Qg2[(size_t)(qbase + r    )*32 + kk*8 + c    ];
        qf[kk][1] = Qg2[(size_t)(qbase + r + 8)*32 + kk*8 + c    ];
        qf[kk][2] = Qg2[(size_t)(qbase + r    )*32 + kk*8 + c + 4];
        qf[kk][3] = Qg2[(size_t)(qbase + r + 8)*32 + kk*8 + c + 4];
    }

    const int k_key_off = ((lane >> 4) & 1) * 8 + (lane & 7);
    const int k_ch_off  = (lane >> 3) & 1;
    const int v_key_off = ((lane >> 3) & 1) * 8 + (lane & 7);
    const int v_ch_off  = (lane >> 4);

    const uint32_t ones2[2] = { 0x3C003C00u, 0x3C003C00u };  // fp16 1.0 x2

    float of[8][4];
    #pragma unroll
    for (int nt = 0; nt < 8; nt++)
        #pragma unroll
        for (int j = 0; j < 4; j++) of[nt][j] = 0.f;
    float lc[4] = {0.f, 0.f, 0.f, 0.f};   // row-sum accumulator (P @ ones)
    float m0i = -1e30f, m1i = -1e30f;

    auto stage = [&](int kt, int s) {
        const uint32_t sb = sbase + (uint32_t)s * ASTG;
        #pragma unroll
        for (int j = 0; j < 2; j++) {
            const int id  = tid + j*256;
            const int row = id >> 3;
            const int ch  = id & 7;
            const uint32_t sw = (uint32_t)(row*128 + ((ch ^ (row & 7))*16));
            cp_async16(sb + sw,          Kg + (size_t)(kt*64 + row)*HDIM + ch*8);
            cp_async16(sb + 8192u + sw,  Vg + (size_t)(kt*64 + row)*HDIM + ch*8);
        }
        asm volatile("cp.async.commit_group;" ::: "memory");
    };

    const int ktmax = 2*qt + 1;
    stage(0, 0);

    for (int kt = 0; kt <= ktmax; kt++) {
        asm volatile("cp.async.wait_group 0;" ::: "memory");
        __syncthreads();
        if (kt < ktmax) stage(kt + 1, (kt + 1) & 1);

        if (kt*64 > qbase + 15) continue;

        const uint32_t sK = sbase + (uint32_t)(kt & 1) * ASTG;
        const uint32_t sV = sK + 8192u;

        // ---- S = Q @ K^T (log2 domain) ----
        float sf[8][4];
        #pragma unroll
        for (int nt = 0; nt < 8; nt++)
            #pragma unroll
            for (int j = 0; j < 4; j++) sf[nt][j] = 0.f;

        #pragma unroll
        for (int kk = 0; kk < 4; kk++) {
            #pragma unroll
            for (int ntp = 0; ntp < 4; ntp++) {
                const int key = ntp*16 + k_key_off;
                const int ch  = 2*kk + k_ch_off;
                uint32_t t[4];
                ldsm_x4(t, sK + (uint32_t)(key*128 + ((ch ^ (key & 7))*16)));
                mma_f16(sf[2*ntp    ], qf[kk], &t[0], sf[2*ntp    ]);
                mma_f16(sf[2*ntp + 1], qf[kk], &t[2], sf[2*ntp + 1]);
            }
        }

        // ---- causal mask (boundary tiles only) ----
        const int qg0 = qbase + r;
        const int qg1 = qg0 + 8;
        if (kt*64 + 63 > qbase) {
            #pragma unroll
            for (int nt = 0; nt < 8; nt++) {
                const int col0 = kt*64 + nt*8 + c*2;
                if (col0     > qg0) sf[nt][0] = -1e30f;
                if (col0 + 1 > qg0) sf[nt][1] = -1e30f;
                if (col0     > qg1) sf[nt][2] = -1e30f;
                if (col0 + 1 > qg1) sf[nt][3] = -1e30f;
            }
        }

        // ---- online softmax (base-2, packed fp16 exp) ----
        float mx0 = -1e30f, mx1 = -1e30f;
        #pragma unroll
        for (int nt = 0; nt < 8; nt++) {
            mx0 = fmaxf(mx0, fmaxf(sf[nt][0], sf[nt][1]));
            mx1 = fmaxf(mx1, fmaxf(sf[nt][2], sf[nt][3]));
        }
        mx0 = fmaxf(mx0, __shfl_xor_sync(0xffffffffu, mx0, 1));
        mx0 = fmaxf(mx0, __shfl_xor_sync(0xffffffffu, mx0, 2));
        mx1 = fmaxf(mx1, __shfl_xor_sync(0xffffffffu, mx1, 1));
        mx1 = fmaxf(mx1, __shfl_xor_sync(0xffffffffu, mx1, 2));

        const float mn0 = fmaxf(m0i, mx0);
        const float mn1 = fmaxf(m1i, mx1);

        // packed exp: cvt pair -> HSUB2 broadcast max -> ex2.approx.f16x2
        const uint32_t mn0h2 = f2h2(mn0, mn0);
        const uint32_t mn1h2 = f2h2(mn1, mn1);
        uint32_t pk[4][4];
        #pragma unroll
        for (int nt = 0; nt < 8; nt++) {
            const uint32_t a = f2h2(sf[nt][0], sf[nt][1]);   // row0 pair
            const uint32_t b = f2h2(sf[nt][2], sf[nt][3]);   // row1 pair
            pk[nt >> 1][(nt & 1)*2    ] = ex2h2(hsub2(a, mn0h2));
            pk[nt >> 1][(nt & 1)*2 + 1] = ex2h2(hsub2(b, mn1h2));
        }

        // rescale accumulators only when a max moved (exact skip: cor==1)
        const bool chg = (mn0 > m0i) || (mn1 > m1i);
        if (__any_sync(0xffffffffu, chg)) {
            const float cor0 = exp2f(m0i - mn0);
            const float cor1 = exp2f(m1i - mn1);
            lc[0] *= cor0; lc[1] *= cor0; lc[2] *= cor1; lc[3] *= cor1;
            #pragma unroll
            for (int nt = 0; nt < 8; nt++) {
                of[nt][0] *= cor0;
                of[nt][1] *= cor0;
                of[nt][2] *= cor1;
                of[nt][3] *= cor1;
            }
        }
        m0i = mn0;
        m1i = mn1;

        // l += P @ ones (tensor pipe; lanes get their rows' sums in lc[0]/lc[2])
        #pragma unroll
        for (int kk = 0; kk < 4; kk++)
            mma_f16(lc, pk[kk], ones2, lc);

        // ---- O += P @ V ----
        #pragma unroll
        for (int kk = 0; kk < 4; kk++) {
            #pragma unroll
            for (int ntp = 0; ntp < 4; ntp++) {
                const int key = 16*kk + v_key_off;
                const int ch  = 2*ntp + v_ch_off;
                uint32_t t[4];
                ldsm_x4_t(t, sV + (uint32_t)(key*128 + ((ch ^ (key & 7))*16)));
                mma_f16(of[2*ntp    ], pk[kk], &t[0], of[2*ntp    ]);
                mma_f16(of[2*ntp + 1], pk[kk], &t[2], of[2*ntp + 1]);
            }
        }
    }

    // epilogue: normalize, write ctx (fp16) [b][s][h*64+d]
    const int b = bh >> 4, h = bh & 15;
    const float inv0 = 1.0f / lc[0];
    const float inv1 = 1.0f / lc[2];
    const int qg0 = qbase + r;
    #pragma unroll
    for (int nt = 0; nt < 8; nt++) {
        const int d = nt*8 + c*2;
        *reinterpret_cast<uint32_t*>(
            g_ctx + ((size_t)(b*SS + qg0    ))*DD + h*HDIM + d) = f2h2(of[nt][0]*inv0, of[nt][1]*inv0);
        *reinterpret_cast<uint32_t*>(
            g_ctx + ((size_t)(b*SS + qg0 + 8))*DD + h*HDIM + d) = f2h2(of[nt][2]*inv1, of[nt][3]*inv1);
    }
}

// ---------------------------------------------------------------------------
// Launch
// ---------------------------------------------------------------------------
extern "C" void kernel_launch(void* const* d_in, const int* in_sizes, int n_in,
                              void* d_out, int out_size)
{
    const float* x  = (const float*)d_in[0];
    const float* Wq = (const float*)d_in[1];
    const float* Wk = (const float*)d_in[2];
    const float* Wv = (const float*)d_in[3];
    const float* Wo = (const float*)d_in[4];
    const float* bo = (const float*)d_in[5];
    float* out = (float*)d_out;

    (void)in_sizes; (void)n_in; (void)out_size;

    __half* dx;  cudaGetSymbolAddress((void**)&dx,  g_x16);
    __half* dwq; cudaGetSymbolAddress((void**)&dwq, g_wq16);
    __half* dwk; cudaGetSymbolAddress((void**)&dwk, g_wk16);
    __half* dwv; cudaGetSymbolAddress((void**)&dwv, g_wv16);
    __half* dwo; cudaGetSymbolAddress((void**)&dwo, g_wo16);

    const int nseg = DD*DD/4;   // 256K float4 per segment
    cvt_all_kernel<<<dim3(nseg/256, 8), 256>>>(
        (const float4*)x,
        (const float4*)Wq, (const float4*)Wk, (const float4*)Wv, (const float4*)Wo,
        (uint2*)dx, (uint2*)dwq, (uint2*)dwk, (uint2*)dwv, (uint2*)dwo);

    const int gsm = 2 * GSTG;   // 196608 bytes dynamic smem (2-stage BK=128)
    cudaFuncSetAttribute(qkv_gemm_kernel,
                         cudaFuncAttributeMaxDynamicSharedMemorySize, gsm);
    cudaFuncSetAttribute(oproj_kernel,
                         cudaFuncAttributeMaxDynamicSharedMemorySize, gsm);

    qkv_gemm_kernel<<<dim3(4, 32, 3), 256, gsm>>>();
    attn_kernel<<<dim3(32, 16), 256>>>();
    oproj_kernel<<<dim3(4, 32), 256, gsm>>>(bo, out);
}